// round 6
// baseline (speedup 1.0000x reference)
#include <cuda_runtime.h>
#include <cuda_bf16.h>

#define N_   20000
#define E_   320000
#define B_   128
#define L_   2
#define SLOPE 0.2f
#define EPS_  1e-5f

// ---------------- scratch (static device allocations) ----------------
__device__ int   g_counts[N_];
__device__ int   g_rowptr[N_ + 1];
__device__ int   g_cursor[N_];
__device__ int2  g_csr2[E_];          // (src, edge_id) per CSR slot

__device__ float g_wea[L_][128][2];   // collapsed W_e * att_e
__device__ float g_inse[L_][B_][2];   // ins part of ae per graph

__device__ float2 g_ae[L_][E_];       // edge attention term, EDGE order
__device__ __nv_bfloat16 g_xlb[(size_t)N_ * 128];
__device__ float g_alr[N_ * 4];       // al0, al1, ar0, ar1
__device__ float g_h[(size_t)N_ * 64];
__device__ float g_bnstats[128];      // sum[64], sumsq[64]

// ---------------- CSR build ----------------
__global__ void zero_kernel() {
    int i = blockIdx.x * blockDim.x + threadIdx.x;
    if (i < N_) g_counts[i] = 0;
    if (i < 128) g_bnstats[i] = 0.f;
}

__global__ void hist_kernel(const int* __restrict__ dst) {
    int i = blockIdx.x * blockDim.x + threadIdx.x;
    if (i < E_) atomicAdd(&g_counts[dst[i]], 1);
}

// single block, 1024 threads, 20 elems per thread (serial) + one block scan
__global__ void scan_kernel() {
    __shared__ int sums[1024];
    const int C = 20;                  // 1024*20 = 20480 >= N_
    int t = threadIdx.x;
    int base = t * C;
    int vals[C];
    int run = 0;
    #pragma unroll
    for (int i = 0; i < C; i++) {
        int idx = base + i;
        int v = (idx < N_) ? g_counts[idx] : 0;
        run += v;
        vals[i] = run;                 // thread-local inclusive
    }
    sums[t] = run;
    __syncthreads();
    for (int o = 1; o < 1024; o <<= 1) {
        int x = (t >= o) ? sums[t - o] : 0;
        __syncthreads();
        sums[t] += x;
        __syncthreads();
    }
    int off = sums[t] - run;           // exclusive prefix of this thread's chunk
    if (t == 0) g_rowptr[0] = 0;
    #pragma unroll
    for (int i = 0; i < C; i++) {
        int idx = base + i;
        if (idx < N_) {
            int incl = off + vals[i];
            int cnt  = vals[i] - (i ? vals[i - 1] : 0);
            g_rowptr[idx + 1] = incl;
            g_cursor[idx]     = incl - cnt;
        }
    }
}

__global__ void scatter_kernel(const int* __restrict__ src, const int* __restrict__ dst) {
    int i = blockIdx.x * blockDim.x + threadIdx.x;
    if (i < E_) {
        int d = dst[i];
        int pos = atomicAdd(&g_cursor[d], 1);
        g_csr2[pos] = make_int2(src[i], i);
    }
}

// ---------------- setup: collapse W_e*att_e + edge ins dots ----------------
__global__ void setup_kernel(const float* __restrict__ W_e,
                             const float* __restrict__ att_e,
                             const float* __restrict__ instr) {
    int tid = threadIdx.x;             // 256 threads, 1 block
    for (int idx = tid; idx < L_ * 128 * 2; idx += 256) {
        int l = idx >> 8;
        int k = (idx >> 1) & 127;
        int h = idx & 1;
        const float* wrow = W_e + ((size_t)l * 128 + k) * 128 + h * 64;
        const float* arow = att_e + l * 128 + h * 64;
        float s = 0.f;
        #pragma unroll 8
        for (int c = 0; c < 64; c++) s += wrow[c] * arow[c];
        g_wea[l][k][h] = s;
    }
    __syncthreads();
    for (int idx = tid; idx < L_ * B_ * 2; idx += 256) {
        int l = idx >> 8;
        int b = (idx >> 1) & 127;
        int h = idx & 1;
        const float* iv = instr + ((size_t)l * B_ + b) * 64;
        float s = 0.f;
        #pragma unroll 8
        for (int k = 0; k < 64; k++) s += iv[k] * g_wea[l][64 + k][h];
        g_inse[l][b][h] = s;
    }
}

// ---------------- ae: both layers, 4 edges per warp, edge-order output ----------------
__global__ void ae_kernel(const float* __restrict__ edge_attr,
                          const int* __restrict__ srcv,
                          const int* __restrict__ batch) {
    __shared__ float swe[L_][64][2];
    int tid = threadIdx.x;
    for (int i = tid; i < L_ * 64 * 2; i += 256) {
        int l = i >> 7, rem = i & 127;
        swe[l][rem >> 1][rem & 1] = g_wea[l][rem >> 1][rem & 1];
    }
    __syncthreads();
    int lane = tid & 31;
    int sub = lane >> 3, l8 = lane & 7;
    int nwarps = gridDim.x * 8;
    for (int warp = blockIdx.x * 8 + (tid >> 5); warp < E_ / 4; warp += nwarps) {
        int e = warp * 4 + sub;
        const float* row = edge_attr + (size_t)e * 64;
        float4 v0 = *(const float4*)(row + l8 * 4);
        float4 v1 = *(const float4*)(row + 32 + l8 * 4);
        float vv[8] = {v0.x, v0.y, v0.z, v0.w, v1.x, v1.y, v1.z, v1.w};
        int k0 = l8 * 4;
        float acc[4] = {0.f, 0.f, 0.f, 0.f};
        #pragma unroll
        for (int j = 0; j < 8; j++) {
            int k = (j < 4) ? (k0 + j) : (32 + k0 + j - 4);
            #pragma unroll
            for (int l = 0; l < 2; l++)
                #pragma unroll
                for (int h = 0; h < 2; h++)
                    acc[l * 2 + h] += vv[j] * swe[l][k][h];
        }
        #pragma unroll
        for (int o = 4; o; o >>= 1) {
            #pragma unroll
            for (int c = 0; c < 4; c++)
                acc[c] += __shfl_xor_sync(0xffffffffu, acc[c], o);
        }
        if (l8 == 0) {
            int b = batch[srcv[e]];
            g_ae[0][e] = make_float2(acc[0] + g_inse[0][b][0], acc[1] + g_inse[0][b][1]);
            g_ae[1][e] = make_float2(acc[2] + g_inse[1][b][0], acc[3] + g_inse[1][b][1]);
        }
    }
}

// ---------------- xl GEMM, bf16 output, fused alr epilogue, optional fused BN ----------------
#define GEMM_SHM ((128 * 68 + 128 * 128) * 4)
__global__ void gemm_xl(const float* __restrict__ hin,
                        const float* __restrict__ Wl,
                        const float* __restrict__ ins,
                        const int* __restrict__ batch,
                        const float* __restrict__ attL,
                        const float* __restrict__ attR,
                        int bn,
                        const float* __restrict__ gamma,
                        const float* __restrict__ beta) {
    extern __shared__ float sh[];
    float* As = sh;                 // [128][68], k-major (transposed)
    float* Ws = sh + 128 * 68;      // [128][128], k-major
    __shared__ int   sbatch[64];
    __shared__ float s_sc[64], s_sh[64];
    int tid = threadIdx.x;
    int node0 = blockIdx.x * 64;
    int rows = min(64, N_ - node0);
    if (tid < 64) sbatch[tid] = (tid < rows) ? batch[node0 + tid] : 0;
    if (bn && tid >= 64 && tid < 128) {
        int c = tid - 64;
        float mu  = g_bnstats[c] * (1.f / N_);
        float var = g_bnstats[64 + c] * (1.f / N_) - mu * mu;
        float inv = rsqrtf(var + EPS_);
        float sc = inv * gamma[c];
        s_sc[c] = sc;
        s_sh[c] = beta[c] - mu * sc;
    }
    const float4* Wg = (const float4*)Wl;
    float4* Ws4 = (float4*)Ws;
    for (int i = tid; i < 128 * 32; i += 256) Ws4[i] = Wg[i];
    __syncthreads();
    for (int i = tid; i < 64 * 128; i += 256) {
        int m = i >> 7, k = i & 127;
        float v = 0.f;
        if (m < rows) {
            if (k < 64) {
                v = hin[(size_t)(node0 + m) * 64 + k];
                if (bn) { v = v * s_sc[k] + s_sh[k]; v = v > 0.f ? v : 0.f; }
            } else {
                v = ins[(size_t)sbatch[m] * 64 + (k - 64)];
            }
        }
        As[k * 68 + m] = v;
    }
    __syncthreads();
    int rt = tid >> 5, lane = tid & 31;
    float acc[8][4];
    #pragma unroll
    for (int r = 0; r < 8; r++)
        #pragma unroll
        for (int j = 0; j < 4; j++) acc[r][j] = 0.f;
    #pragma unroll 4
    for (int k = 0; k < 128; k++) {
        const float* ar = As + k * 68 + rt * 8;
        float4 a0 = *(const float4*)ar;
        float4 a1 = *(const float4*)(ar + 4);
        float4 b  = *(const float4*)(Ws + k * 128 + lane * 4);
        float av[8] = {a0.x, a0.y, a0.z, a0.w, a1.x, a1.y, a1.z, a1.w};
        #pragma unroll
        for (int r = 0; r < 8; r++) {
            acc[r][0] += av[r] * b.x;
            acc[r][1] += av[r] * b.y;
            acc[r][2] += av[r] * b.z;
            acc[r][3] += av[r] * b.w;
        }
    }
    #pragma unroll
    for (int r = 0; r < 8; r++) {
        int m = rt * 8 + r;
        if (m < rows) {
            __nv_bfloat162 b0 = __float22bfloat162_rn(make_float2(acc[r][0], acc[r][1]));
            __nv_bfloat162 b1 = __float22bfloat162_rn(make_float2(acc[r][2], acc[r][3]));
            uint2 v;
            v.x = *(unsigned*)&b0;
            v.y = *(unsigned*)&b1;
            *(uint2*)(g_xlb + (size_t)(node0 + m) * 128 + lane * 4) = v;
        }
    }
    // fused alr epilogue (fp32 accumulators): al = xl.att_l, ar = xl.att_r
    float4 atl = *(const float4*)(attL + lane * 4);
    float4 atr = *(const float4*)(attR + lane * 4);
    #pragma unroll
    for (int r = 0; r < 8; r++) {
        float pl = acc[r][0] * atl.x + acc[r][1] * atl.y + acc[r][2] * atl.z + acc[r][3] * atl.w;
        float pr = acc[r][0] * atr.x + acc[r][1] * atr.y + acc[r][2] * atr.z + acc[r][3] * atr.w;
        #pragma unroll
        for (int o = 8; o; o >>= 1) {
            pl += __shfl_xor_sync(0xffffffffu, pl, o);
            pr += __shfl_xor_sync(0xffffffffu, pr, o);
        }
        float pl1 = __shfl_sync(0xffffffffu, pl, 16);
        float pr1 = __shfl_sync(0xffffffffu, pr, 16);
        int m = rt * 8 + r;
        if (lane == 0 && m < rows) {
            float4 v = {pl, pl1, pr, pr1};
            *(float4*)(g_alr + (size_t)(node0 + m) * 4) = v;
        }
    }
}

// ---------------- per-node softmax + aggregation; register-resident fast path ----------------
__global__ void agg_kernel(int layer, const float* __restrict__ hin,
                           float* __restrict__ hout,
                           const float* __restrict__ bias, int do_stats,
                           int bn_resid,
                           const float* __restrict__ gamma,
                           const float* __restrict__ beta) {
    __shared__ float s_sum[64], s_sq[64], s_sc[64], s_sh[64];
    int tid = threadIdx.x;
    if (do_stats && tid < 64) { s_sum[tid] = 0.f; s_sq[tid] = 0.f; }
    if (bn_resid && tid < 64) {
        float mu  = g_bnstats[tid] * (1.f / N_);
        float var = g_bnstats[64 + tid] * (1.f / N_) - mu * mu;
        float inv = rsqrtf(var + EPS_);
        float sc = inv * gamma[tid];
        s_sc[tid] = sc;
        s_sh[tid] = beta[tid] - mu * sc;
    }
    __syncthreads();
    const unsigned FULL = 0xffffffffu;
    int lane = tid & 31;
    bool head1 = lane >= 16;
    int coff = lane * 4;               // meaningful for lanes 0-15 at writeback
    const float2* aep = g_ae[layer];
    const float* bz = bias + layer * 64;
    const __nv_bfloat16* xlb = g_xlb;
    int nwarps = gridDim.x * 8;
    for (int node = blockIdx.x * 8 + (tid >> 5); node < N_; node += nwarps) {
        int start = g_rowptr[node], end = g_rowptr[node + 1];
        int ec = end - start;
        float2 arr = *(const float2*)&g_alr[node * 4 + 2];
        float acc0 = 0.f, acc1 = 0.f, acc2 = 0.f, acc3 = 0.f;
        float sc0, sc1;
        if (ec <= 32) {
            // ---- fast path: whole row resident in warp registers ----
            int sidx = 0;
            float a0 = -1e30f, a1 = -1e30f;
            if (lane < ec) {
                int2 se = g_csr2[start + lane];
                sidx = se.x;
                float2 al = *(const float2*)&g_alr[sidx * 4];
                float2 ae = aep[se.y];
                a0 = al.x + arr.x + ae.x; a0 = fmaxf(a0, SLOPE * a0);
                a1 = al.y + arr.y + ae.y; a1 = fmaxf(a1, SLOPE * a1);
            }
            float m0 = a0, m1 = a1;
            #pragma unroll
            for (int o = 16; o; o >>= 1) {
                m0 = fmaxf(m0, __shfl_xor_sync(FULL, m0, o));
                m1 = fmaxf(m1, __shfl_xor_sync(FULL, m1, o));
            }
            float e0 = (lane < ec) ? __expf(a0 - m0) : 0.f;
            float e1 = (lane < ec) ? __expf(a1 - m1) : 0.f;
            float s0 = e0, s1 = e1;
            #pragma unroll
            for (int o = 16; o; o >>= 1) {
                s0 += __shfl_xor_sync(FULL, s0, o);
                s1 += __shfl_xor_sync(FULL, s1, o);
            }
            sc0 = 1.f / (s0 + 1e-16f);
            sc1 = 1.f / (s1 + 1e-16f);
            #pragma unroll 4
            for (int e = 0; e < ec; e++) {
                // broadcast BOTH head weights from lane e, select by receiver's head
                float w0 = __shfl_sync(FULL, e0, e);
                float w1 = __shfl_sync(FULL, e1, e);
                int   sE = __shfl_sync(FULL, sidx, e);
                float w  = head1 ? w1 : w0;
                uint2 raw = *(const uint2*)(xlb + (size_t)sE * 128 + lane * 4);
                float2 x01 = __bfloat1622float2(*(const __nv_bfloat162*)&raw.x);
                float2 x23 = __bfloat1622float2(*(const __nv_bfloat162*)&raw.y);
                acc0 += w * x01.x; acc1 += w * x01.y;
                acc2 += w * x23.x; acc3 += w * x23.y;
            }
        } else {
            // ---- slow path (rare: row > 32 edges) ----
            float m0 = -1e30f, m1 = -1e30f;
            for (int p = start + lane; p < end; p += 32) {
                int2 se = g_csr2[p];
                float2 al = *(const float2*)&g_alr[se.x * 4];
                float2 ae = aep[se.y];
                float a0 = al.x + arr.x + ae.x; a0 = fmaxf(a0, SLOPE * a0);
                float a1 = al.y + arr.y + ae.y; a1 = fmaxf(a1, SLOPE * a1);
                m0 = fmaxf(m0, a0); m1 = fmaxf(m1, a1);
            }
            #pragma unroll
            for (int o = 16; o; o >>= 1) {
                m0 = fmaxf(m0, __shfl_xor_sync(FULL, m0, o));
                m1 = fmaxf(m1, __shfl_xor_sync(FULL, m1, o));
            }
            float s0 = 0.f, s1 = 0.f;
            for (int p = start + lane; p < end; p += 32) {
                int2 se = g_csr2[p];
                float2 al = *(const float2*)&g_alr[se.x * 4];
                float2 ae = aep[se.y];
                float a0 = al.x + arr.x + ae.x; a0 = fmaxf(a0, SLOPE * a0);
                float a1 = al.y + arr.y + ae.y; a1 = fmaxf(a1, SLOPE * a1);
                s0 += __expf(a0 - m0); s1 += __expf(a1 - m1);
            }
            #pragma unroll
            for (int o = 16; o; o >>= 1) {
                s0 += __shfl_xor_sync(FULL, s0, o);
                s1 += __shfl_xor_sync(FULL, s1, o);
            }
            sc0 = 1.f / (s0 + 1e-16f);
            sc1 = 1.f / (s1 + 1e-16f);
            float mh = head1 ? m1 : m0;
            for (int p = start; p < end; p++) {
                int2 se = g_csr2[p];                    // warp-uniform broadcast
                float2 al = *(const float2*)&g_alr[se.x * 4];
                float2 ae = aep[se.y];
                float a0 = al.x + arr.x + ae.x; a0 = fmaxf(a0, SLOPE * a0);
                float a1 = al.y + arr.y + ae.y; a1 = fmaxf(a1, SLOPE * a1);
                float w = __expf((head1 ? a1 : a0) - mh);   // per-lane head select, no shuffle
                uint2 raw = *(const uint2*)(xlb + (size_t)se.x * 128 + lane * 4);
                float2 x01 = __bfloat1622float2(*(const __nv_bfloat162*)&raw.x);
                float2 x23 = __bfloat1622float2(*(const __nv_bfloat162*)&raw.y);
                acc0 += w * x01.x; acc1 += w * x01.y;
                acc2 += w * x23.x; acc3 += w * x23.y;
            }
        }
        float sc = head1 ? sc1 : sc0;
        float o0 = acc0 * sc, o1 = acc1 * sc, o2 = acc2 * sc, o3 = acc3 * sc;
        float p0 = __shfl_xor_sync(FULL, o0, 16);
        float p1 = __shfl_xor_sync(FULL, o1, 16);
        float p2 = __shfl_xor_sync(FULL, o2, 16);
        float p3 = __shfl_xor_sync(FULL, o3, 16);
        if (!head1) {
            float4 hv = *(const float4*)(hin + (size_t)node * 64 + coff);
            if (bn_resid) {
                hv.x = fmaxf(hv.x * s_sc[coff + 0] + s_sh[coff + 0], 0.f);
                hv.y = fmaxf(hv.y * s_sc[coff + 1] + s_sh[coff + 1], 0.f);
                hv.z = fmaxf(hv.z * s_sc[coff + 2] + s_sh[coff + 2], 0.f);
                hv.w = fmaxf(hv.w * s_sc[coff + 3] + s_sh[coff + 3], 0.f);
            }
            float4 bv = *(const float4*)(bz + coff);
            float r0 = (o0 + p0) * 0.5f + bv.x + hv.x;
            float r1 = (o1 + p1) * 0.5f + bv.y + hv.y;
            float r2 = (o2 + p2) * 0.5f + bv.z + hv.z;
            float r3 = (o3 + p3) * 0.5f + bv.w + hv.w;
            float4 res = {r0, r1, r2, r3};
            *(float4*)(hout + (size_t)node * 64 + coff) = res;
            if (do_stats) {
                atomicAdd(&s_sum[coff + 0], r0); atomicAdd(&s_sq[coff + 0], r0 * r0);
                atomicAdd(&s_sum[coff + 1], r1); atomicAdd(&s_sq[coff + 1], r1 * r1);
                atomicAdd(&s_sum[coff + 2], r2); atomicAdd(&s_sq[coff + 2], r2 * r2);
                atomicAdd(&s_sum[coff + 3], r3); atomicAdd(&s_sq[coff + 3], r3 * r3);
            }
        }
    }
    if (do_stats) {
        __syncthreads();
        if (tid < 64) {
            atomicAdd(&g_bnstats[tid],      s_sum[tid]);
            atomicAdd(&g_bnstats[64 + tid], s_sq[tid]);
        }
    }
}

// ---------------- launch (single stream — no stream/event objects) ----------------
extern "C" void kernel_launch(void* const* d_in, const int* in_sizes, int n_in,
                              void* d_out, int out_size) {
    const float* x         = (const float*)d_in[0];
    const int*   eidx      = (const int*)d_in[1];
    const float* edge_attr = (const float*)d_in[2];
    const float* instr     = (const float*)d_in[3];
    const int*   batch     = (const int*)d_in[4];
    const float* W_l       = (const float*)d_in[5];
    const float* W_e       = (const float*)d_in[6];
    const float* att_l     = (const float*)d_in[7];
    const float* att_r     = (const float*)d_in[8];
    const float* att_e     = (const float*)d_in[9];
    const float* bias      = (const float*)d_in[10];
    const float* bn_gamma  = (const float*)d_in[11];
    const float* bn_beta   = (const float*)d_in[12];
    float* out = (float*)d_out;

    const int* src = eidx;
    const int* dst = eidx + E_;

    float* h_ptr = nullptr;
    cudaGetSymbolAddress((void**)&h_ptr, g_h);
    cudaFuncSetAttribute(gemm_xl, cudaFuncAttributeMaxDynamicSharedMemorySize, GEMM_SHM);

    // CSR build
    zero_kernel<<<(N_ + 255) / 256, 256>>>();
    hist_kernel<<<(E_ + 255) / 256, 256>>>(dst);
    scan_kernel<<<1, 1024>>>();
    scatter_kernel<<<(E_ + 255) / 256, 256>>>(src, dst);

    // edge-attention path (edge order)
    setup_kernel<<<1, 256>>>(W_e, att_e, instr);
    ae_kernel<<<592, 256>>>(edge_attr, src, batch);

    // layer 0: GEMM (+alr epilogue), aggregation (collect BN stats)
    gemm_xl<<<(N_ + 63) / 64, 256, GEMM_SHM>>>(x, W_l, instr, batch,
                                               att_l, att_r, 0, nullptr, nullptr);
    agg_kernel<<<1280, 256>>>(0, x, h_ptr, bias, 1, 0, nullptr, nullptr);

    // layer 1: GEMM with fused BN+relu on input, agg with fused BN+relu on residual
    gemm_xl<<<(N_ + 63) / 64, 256, GEMM_SHM>>>(h_ptr, W_l + 128 * 128, instr + B_ * 64, batch,
                                               att_l + 128, att_r + 128, 1, bn_gamma, bn_beta);
    agg_kernel<<<1280, 256>>>(1, h_ptr, out, bias, 0, 1, bn_gamma, bn_beta);
}

// round 7
// speedup vs baseline: 1.1910x; 1.1910x over previous
#include <cuda_runtime.h>
#include <cuda_bf16.h>

#define N_   20000
#define E_   320000
#define B_   128
#define L_   2
#define SLOPE 0.2f
#define EPS_  1e-5f

// ---------------- scratch (static device allocations) ----------------
__device__ int   g_counts[N_];
__device__ int   g_rowptr[N_ + 1];
__device__ int   g_cursor[N_];
__device__ int   g_csr_src[E_];
__device__ int   g_perm[E_];

__device__ float g_wea[L_][128][2];   // collapsed W_e * att_e
__device__ float g_inse[L_][B_][2];   // ins part of ae per graph

__device__ float2 g_ae[L_][E_];       // edge attention term, CSR-permuted
__device__ float2 g_att[E_];          // scratch: post-leaky logits
__device__ __nv_bfloat16 g_xlb[(size_t)N_ * 128];
__device__ float g_alr[N_ * 4];       // al0, al1, ar0, ar1
__device__ float g_h[(size_t)N_ * 64];
__device__ float g_bnstats[128];      // sum[64], sumsq[64]

// ---------------- CSR build ----------------
__global__ void zero_kernel() {
    int i = blockIdx.x * blockDim.x + threadIdx.x;
    if (i < N_) g_counts[i] = 0;
    if (i < 128) g_bnstats[i] = 0.f;
}

__global__ void hist_kernel(const int* __restrict__ dst) {
    int i = blockIdx.x * blockDim.x + threadIdx.x;
    if (i < E_) atomicAdd(&g_counts[dst[i]], 1);
}

// single block, 1024 threads, 20 elems per thread (serial) + one block scan
__global__ void scan_kernel() {
    __shared__ int sums[1024];
    const int C = 20;                  // 1024*20 = 20480 >= N_
    int t = threadIdx.x;
    int base = t * C;
    int vals[C];
    int run = 0;
    #pragma unroll
    for (int i = 0; i < C; i++) {
        int idx = base + i;
        int v = (idx < N_) ? g_counts[idx] : 0;
        run += v;
        vals[i] = run;                 // thread-local inclusive
    }
    sums[t] = run;
    __syncthreads();
    for (int o = 1; o < 1024; o <<= 1) {
        int x = (t >= o) ? sums[t - o] : 0;
        __syncthreads();
        sums[t] += x;
        __syncthreads();
    }
    int off = sums[t] - run;           // exclusive prefix of this thread's chunk
    if (t == 0) g_rowptr[0] = 0;
    #pragma unroll
    for (int i = 0; i < C; i++) {
        int idx = base + i;
        if (idx < N_) {
            int incl = off + vals[i];
            int cnt  = vals[i] - (i ? vals[i - 1] : 0);
            g_rowptr[idx + 1] = incl;
            g_cursor[idx]     = incl - cnt;
        }
    }
}

__global__ void scatter_kernel(const int* __restrict__ src, const int* __restrict__ dst) {
    int i = blockIdx.x * blockDim.x + threadIdx.x;
    if (i < E_) {
        int d = dst[i];
        int pos = atomicAdd(&g_cursor[d], 1);
        g_csr_src[pos] = src[i];
        g_perm[i] = pos;
    }
}

// ---------------- setup: collapse W_e*att_e + edge ins dots ----------------
__global__ void setup_kernel(const float* __restrict__ W_e,
                             const float* __restrict__ att_e,
                             const float* __restrict__ instr) {
    int tid = threadIdx.x;             // 256 threads, 1 block
    for (int idx = tid; idx < L_ * 128 * 2; idx += 256) {
        int l = idx >> 8;
        int k = (idx >> 1) & 127;
        int h = idx & 1;
        const float* wrow = W_e + ((size_t)l * 128 + k) * 128 + h * 64;
        const float* arow = att_e + l * 128 + h * 64;
        float s = 0.f;
        #pragma unroll 8
        for (int c = 0; c < 64; c++) s += wrow[c] * arow[c];
        g_wea[l][k][h] = s;
    }
    __syncthreads();
    for (int idx = tid; idx < L_ * B_ * 2; idx += 256) {
        int l = idx >> 8;
        int b = (idx >> 1) & 127;
        int h = idx & 1;
        const float* iv = instr + ((size_t)l * B_ + b) * 64;
        float s = 0.f;
        #pragma unroll 8
        for (int k = 0; k < 64; k++) s += iv[k] * g_wea[l][64 + k][h];
        g_inse[l][b][h] = s;
    }
}

// ---------------- ae: both layers, 4 edges per warp, CSR-permuted output ----------------
__global__ void ae_kernel(const float* __restrict__ edge_attr,
                          const int* __restrict__ srcv,
                          const int* __restrict__ batch) {
    __shared__ float swe[L_][64][2];
    int tid = threadIdx.x;
    for (int i = tid; i < L_ * 64 * 2; i += 256) {
        int l = i >> 7, rem = i & 127;
        swe[l][rem >> 1][rem & 1] = g_wea[l][rem >> 1][rem & 1];
    }
    __syncthreads();
    int lane = tid & 31;
    int sub = lane >> 3, l8 = lane & 7;
    int nwarps = gridDim.x * 8;
    for (int warp = blockIdx.x * 8 + (tid >> 5); warp < E_ / 4; warp += nwarps) {
        int e = warp * 4 + sub;
        const float* row = edge_attr + (size_t)e * 64;
        float4 v0 = *(const float4*)(row + l8 * 4);
        float4 v1 = *(const float4*)(row + 32 + l8 * 4);
        float vv[8] = {v0.x, v0.y, v0.z, v0.w, v1.x, v1.y, v1.z, v1.w};
        int k0 = l8 * 4;
        float acc[4] = {0.f, 0.f, 0.f, 0.f};
        #pragma unroll
        for (int j = 0; j < 8; j++) {
            int k = (j < 4) ? (k0 + j) : (32 + k0 + j - 4);
            #pragma unroll
            for (int l = 0; l < 2; l++)
                #pragma unroll
                for (int h = 0; h < 2; h++)
                    acc[l * 2 + h] += vv[j] * swe[l][k][h];
        }
        #pragma unroll
        for (int o = 4; o; o >>= 1) {
            #pragma unroll
            for (int c = 0; c < 4; c++)
                acc[c] += __shfl_xor_sync(0xffffffffu, acc[c], o);
        }
        if (l8 == 0) {
            int b = batch[srcv[e]];
            int pos = g_perm[e];
            g_ae[0][pos] = make_float2(acc[0] + g_inse[0][b][0], acc[1] + g_inse[0][b][1]);
            g_ae[1][pos] = make_float2(acc[2] + g_inse[1][b][0], acc[3] + g_inse[1][b][1]);
        }
    }
}

// ---------------- xl GEMM, bf16 output, fused alr epilogue, optional fused BN ----------------
#define GEMM_SHM ((128 * 68 + 128 * 128) * 4)
__global__ void gemm_xl(const float* __restrict__ hin,
                        const float* __restrict__ Wl,
                        const float* __restrict__ ins,
                        const int* __restrict__ batch,
                        const float* __restrict__ attL,
                        const float* __restrict__ attR,
                        int bn,
                        const float* __restrict__ gamma,
                        const float* __restrict__ beta) {
    extern __shared__ float sh[];
    float* As = sh;                 // [128][68], k-major (transposed)
    float* Ws = sh + 128 * 68;      // [128][128], k-major
    __shared__ int   sbatch[64];
    __shared__ float s_sc[64], s_sh[64];
    int tid = threadIdx.x;
    int node0 = blockIdx.x * 64;
    int rows = min(64, N_ - node0);
    if (tid < 64) sbatch[tid] = (tid < rows) ? batch[node0 + tid] : 0;
    if (bn && tid >= 64 && tid < 128) {
        int c = tid - 64;
        float mu  = g_bnstats[c] * (1.f / N_);
        float var = g_bnstats[64 + c] * (1.f / N_) - mu * mu;
        float inv = rsqrtf(var + EPS_);
        float sc = inv * gamma[c];
        s_sc[c] = sc;
        s_sh[c] = beta[c] - mu * sc;
    }
    const float4* Wg = (const float4*)Wl;
    float4* Ws4 = (float4*)Ws;
    for (int i = tid; i < 128 * 32; i += 256) Ws4[i] = Wg[i];
    __syncthreads();
    for (int i = tid; i < 64 * 128; i += 256) {
        int m = i >> 7, k = i & 127;
        float v = 0.f;
        if (m < rows) {
            if (k < 64) {
                v = hin[(size_t)(node0 + m) * 64 + k];
                if (bn) { v = v * s_sc[k] + s_sh[k]; v = v > 0.f ? v : 0.f; }
            } else {
                v = ins[(size_t)sbatch[m] * 64 + (k - 64)];
            }
        }
        As[k * 68 + m] = v;
    }
    __syncthreads();
    int rt = tid >> 5, lane = tid & 31;
    float acc[8][4];
    #pragma unroll
    for (int r = 0; r < 8; r++)
        #pragma unroll
        for (int j = 0; j < 4; j++) acc[r][j] = 0.f;
    #pragma unroll 4
    for (int k = 0; k < 128; k++) {
        const float* ar = As + k * 68 + rt * 8;
        float4 a0 = *(const float4*)ar;
        float4 a1 = *(const float4*)(ar + 4);
        float4 b  = *(const float4*)(Ws + k * 128 + lane * 4);
        float av[8] = {a0.x, a0.y, a0.z, a0.w, a1.x, a1.y, a1.z, a1.w};
        #pragma unroll
        for (int r = 0; r < 8; r++) {
            acc[r][0] += av[r] * b.x;
            acc[r][1] += av[r] * b.y;
            acc[r][2] += av[r] * b.z;
            acc[r][3] += av[r] * b.w;
        }
    }
    #pragma unroll
    for (int r = 0; r < 8; r++) {
        int m = rt * 8 + r;
        if (m < rows) {
            __nv_bfloat162 b0 = __float22bfloat162_rn(make_float2(acc[r][0], acc[r][1]));
            __nv_bfloat162 b1 = __float22bfloat162_rn(make_float2(acc[r][2], acc[r][3]));
            uint2 v;
            v.x = *(unsigned*)&b0;
            v.y = *(unsigned*)&b1;
            *(uint2*)(g_xlb + (size_t)(node0 + m) * 128 + lane * 4) = v;
        }
    }
    // fused alr epilogue (fp32 accumulators): al = xl.att_l, ar = xl.att_r
    float4 atl = *(const float4*)(attL + lane * 4);
    float4 atr = *(const float4*)(attR + lane * 4);
    #pragma unroll
    for (int r = 0; r < 8; r++) {
        float pl = acc[r][0] * atl.x + acc[r][1] * atl.y + acc[r][2] * atl.z + acc[r][3] * atl.w;
        float pr = acc[r][0] * atr.x + acc[r][1] * atr.y + acc[r][2] * atr.z + acc[r][3] * atr.w;
        #pragma unroll
        for (int o = 8; o; o >>= 1) {
            pl += __shfl_xor_sync(0xffffffffu, pl, o);
            pr += __shfl_xor_sync(0xffffffffu, pr, o);
        }
        float pl1 = __shfl_sync(0xffffffffu, pl, 16);
        float pr1 = __shfl_sync(0xffffffffu, pr, 16);
        int m = rt * 8 + r;
        if (lane == 0 && m < rows) {
            float4 v = {pl, pl1, pr, pr1};
            *(float4*)(g_alr + (size_t)(node0 + m) * 4) = v;
        }
    }
}

// ---------------- per-node online softmax + aggregation; two-pass via g_att ----------------
__global__ void agg_kernel(int layer, const float* __restrict__ hin,
                           float* __restrict__ hout,
                           const float* __restrict__ bias, int do_stats,
                           int bn_resid,
                           const float* __restrict__ gamma,
                           const float* __restrict__ beta) {
    __shared__ float s_sum[64], s_sq[64], s_sc[64], s_sh[64];
    int tid = threadIdx.x;
    if (do_stats && tid < 64) { s_sum[tid] = 0.f; s_sq[tid] = 0.f; }
    if (bn_resid && tid < 64) {
        float mu  = g_bnstats[tid] * (1.f / N_);
        float var = g_bnstats[64 + tid] * (1.f / N_) - mu * mu;
        float inv = rsqrtf(var + EPS_);
        float sc = inv * gamma[tid];
        s_sc[tid] = sc;
        s_sh[tid] = beta[tid] - mu * sc;
    }
    __syncthreads();
    const unsigned FULL = 0xffffffffu;
    int lane = tid & 31;
    bool head1 = lane >= 16;
    int coff = lane * 4;               // meaningful for lanes 0-15 at writeback
    const float2* aep = g_ae[layer];
    const float* bz = bias + layer * 64;
    const __nv_bfloat16* xlb = g_xlb;
    int nwarps = gridDim.x * 8;
    for (int node = blockIdx.x * 8 + (tid >> 5); node < N_; node += nwarps) {
        int start = g_rowptr[node], end = g_rowptr[node + 1];
        float2 arr = *(const float2*)&g_alr[node * 4 + 2];
        // pass A: online (max, sum), store post-leaky logits coalesced
        float m0 = -1e30f, m1 = -1e30f, s0 = 0.f, s1 = 0.f;
        for (int p = start + lane; p < end; p += 32) {
            int s = g_csr_src[p];
            float2 al = *(const float2*)&g_alr[s * 4];
            float2 ae = aep[p];
            float a0 = al.x + arr.x + ae.x; a0 = fmaxf(a0, SLOPE * a0);
            float a1 = al.y + arr.y + ae.y; a1 = fmaxf(a1, SLOPE * a1);
            g_att[p] = make_float2(a0, a1);
            float nm0 = fmaxf(m0, a0);
            s0 = s0 * __expf(m0 - nm0) + __expf(a0 - nm0); m0 = nm0;
            float nm1 = fmaxf(m1, a1);
            s1 = s1 * __expf(m1 - nm1) + __expf(a1 - nm1); m1 = nm1;
        }
        #pragma unroll
        for (int o = 16; o; o >>= 1) {
            float om0 = __shfl_xor_sync(FULL, m0, o);
            float os0 = __shfl_xor_sync(FULL, s0, o);
            float nm0 = fmaxf(m0, om0);
            s0 = s0 * __expf(m0 - nm0) + os0 * __expf(om0 - nm0); m0 = nm0;
            float om1 = __shfl_xor_sync(FULL, m1, o);
            float os1 = __shfl_xor_sync(FULL, s1, o);
            float nm1 = fmaxf(m1, om1);
            s1 = s1 * __expf(m1 - nm1) + os1 * __expf(om1 - nm1); m1 = nm1;
        }
        float sc0 = 1.f / (s0 + 1e-16f), sc1 = 1.f / (s1 + 1e-16f);
        __threadfence_block();
        __syncwarp();
        // pass B: weighted aggregation, unrolled x4 for MLP, bf16 gathers
        float mh = head1 ? m1 : m0;
        float acc0 = 0.f, acc1 = 0.f, acc2 = 0.f, acc3 = 0.f;
        int p = start;
        for (; p + 3 < end; p += 4) {
            int sA = g_csr_src[p],     sB = g_csr_src[p + 1];
            int sC = g_csr_src[p + 2], sD = g_csr_src[p + 3];
            float2 aA = g_att[p],     aB = g_att[p + 1];
            float2 aC = g_att[p + 2], aD = g_att[p + 3];
            uint2 rA = *(const uint2*)(xlb + (size_t)sA * 128 + lane * 4);
            uint2 rB = *(const uint2*)(xlb + (size_t)sB * 128 + lane * 4);
            uint2 rC = *(const uint2*)(xlb + (size_t)sC * 128 + lane * 4);
            uint2 rD = *(const uint2*)(xlb + (size_t)sD * 128 + lane * 4);
            float wA = __expf((head1 ? aA.y : aA.x) - mh);
            float wB = __expf((head1 ? aB.y : aB.x) - mh);
            float wC = __expf((head1 ? aC.y : aC.x) - mh);
            float wD = __expf((head1 ? aD.y : aD.x) - mh);
            float2 xA0 = __bfloat1622float2(*(const __nv_bfloat162*)&rA.x);
            float2 xA1 = __bfloat1622float2(*(const __nv_bfloat162*)&rA.y);
            float2 xB0 = __bfloat1622float2(*(const __nv_bfloat162*)&rB.x);
            float2 xB1 = __bfloat1622float2(*(const __nv_bfloat162*)&rB.y);
            float2 xC0 = __bfloat1622float2(*(const __nv_bfloat162*)&rC.x);
            float2 xC1 = __bfloat1622float2(*(const __nv_bfloat162*)&rC.y);
            float2 xD0 = __bfloat1622float2(*(const __nv_bfloat162*)&rD.x);
            float2 xD1 = __bfloat1622float2(*(const __nv_bfloat162*)&rD.y);
            acc0 += wA * xA0.x + wB * xB0.x + wC * xC0.x + wD * xD0.x;
            acc1 += wA * xA0.y + wB * xB0.y + wC * xC0.y + wD * xD0.y;
            acc2 += wA * xA1.x + wB * xB1.x + wC * xC1.x + wD * xD1.x;
            acc3 += wA * xA1.y + wB * xB1.y + wC * xC1.y + wD * xD1.y;
        }
        for (; p < end; p++) {
            int s = g_csr_src[p];
            float2 a = g_att[p];
            float w = __expf((head1 ? a.y : a.x) - mh);
            uint2 raw = *(const uint2*)(xlb + (size_t)s * 128 + lane * 4);
            float2 x01 = __bfloat1622float2(*(const __nv_bfloat162*)&raw.x);
            float2 x23 = __bfloat1622float2(*(const __nv_bfloat162*)&raw.y);
            acc0 += w * x01.x; acc1 += w * x01.y;
            acc2 += w * x23.x; acc3 += w * x23.y;
        }
        float sc = head1 ? sc1 : sc0;
        float o0 = acc0 * sc, o1 = acc1 * sc, o2 = acc2 * sc, o3 = acc3 * sc;
        float p0 = __shfl_xor_sync(FULL, o0, 16);
        float p1 = __shfl_xor_sync(FULL, o1, 16);
        float p2 = __shfl_xor_sync(FULL, o2, 16);
        float p3 = __shfl_xor_sync(FULL, o3, 16);
        if (!head1) {
            float4 hv = *(const float4*)(hin + (size_t)node * 64 + coff);
            if (bn_resid) {
                hv.x = fmaxf(hv.x * s_sc[coff + 0] + s_sh[coff + 0], 0.f);
                hv.y = fmaxf(hv.y * s_sc[coff + 1] + s_sh[coff + 1], 0.f);
                hv.z = fmaxf(hv.z * s_sc[coff + 2] + s_sh[coff + 2], 0.f);
                hv.w = fmaxf(hv.w * s_sc[coff + 3] + s_sh[coff + 3], 0.f);
            }
            float4 bv = *(const float4*)(bz + coff);
            float r0 = (o0 + p0) * 0.5f + bv.x + hv.x;
            float r1 = (o1 + p1) * 0.5f + bv.y + hv.y;
            float r2 = (o2 + p2) * 0.5f + bv.z + hv.z;
            float r3 = (o3 + p3) * 0.5f + bv.w + hv.w;
            float4 res = {r0, r1, r2, r3};
            *(float4*)(hout + (size_t)node * 64 + coff) = res;
            if (do_stats) {
                atomicAdd(&s_sum[coff + 0], r0); atomicAdd(&s_sq[coff + 0], r0 * r0);
                atomicAdd(&s_sum[coff + 1], r1); atomicAdd(&s_sq[coff + 1], r1 * r1);
                atomicAdd(&s_sum[coff + 2], r2); atomicAdd(&s_sq[coff + 2], r2 * r2);
                atomicAdd(&s_sum[coff + 3], r3); atomicAdd(&s_sq[coff + 3], r3 * r3);
            }
        }
    }
    if (do_stats) {
        __syncthreads();
        if (tid < 64) {
            atomicAdd(&g_bnstats[tid],      s_sum[tid]);
            atomicAdd(&g_bnstats[64 + tid], s_sq[tid]);
        }
    }
}

// ---------------- launch (R3-proven single-fork pattern) ----------------
extern "C" void kernel_launch(void* const* d_in, const int* in_sizes, int n_in,
                              void* d_out, int out_size) {
    const float* x         = (const float*)d_in[0];
    const int*   eidx      = (const int*)d_in[1];
    const float* edge_attr = (const float*)d_in[2];
    const float* instr     = (const float*)d_in[3];
    const int*   batch     = (const int*)d_in[4];
    const float* W_l       = (const float*)d_in[5];
    const float* W_e       = (const float*)d_in[6];
    const float* att_l     = (const float*)d_in[7];
    const float* att_r     = (const float*)d_in[8];
    const float* att_e     = (const float*)d_in[9];
    const float* bias      = (const float*)d_in[10];
    const float* bn_gamma  = (const float*)d_in[11];
    const float* bn_beta   = (const float*)d_in[12];
    float* out = (float*)d_out;

    const int* src = eidx;
    const int* dst = eidx + E_;

    float* h_ptr = nullptr;
    cudaGetSymbolAddress((void**)&h_ptr, g_h);
    cudaFuncSetAttribute(gemm_xl, cudaFuncAttributeMaxDynamicSharedMemorySize, GEMM_SHM);

    // fork-join: CSR build on one side stream (pattern validated in R3)
    cudaStream_t s2;
    cudaStreamCreateWithFlags(&s2, cudaStreamNonBlocking);
    cudaEvent_t e1, e2;
    cudaEventCreateWithFlags(&e1, cudaEventDisableTiming);
    cudaEventCreateWithFlags(&e2, cudaEventDisableTiming);

    cudaEventRecord(e1, 0);
    cudaStreamWaitEvent(s2, e1, 0);
    zero_kernel<<<(N_ + 255) / 256, 256, 0, s2>>>();
    hist_kernel<<<(E_ + 255) / 256, 256, 0, s2>>>(dst);
    scan_kernel<<<1, 1024, 0, s2>>>();
    scatter_kernel<<<(E_ + 255) / 256, 256, 0, s2>>>(src, dst);
    cudaEventRecord(e2, s2);

    // main stream: layer-0 GEMM + edge-weight setup (independent of CSR)
    gemm_xl<<<(N_ + 63) / 64, 256, GEMM_SHM>>>(x, W_l, instr, batch,
                                               att_l, att_r, 0, nullptr, nullptr);
    setup_kernel<<<1, 256>>>(W_e, att_e, instr);

    cudaStreamWaitEvent(0, e2, 0);     // join CSR branch
    ae_kernel<<<592, 256>>>(edge_attr, src, batch);

    // layer 0 aggregation (collect BN stats)
    agg_kernel<<<1280, 256>>>(0, x, h_ptr, bias, 1, 0, nullptr, nullptr);

    // layer 1: GEMM with fused BN+relu on input, agg with fused BN+relu on residual
    gemm_xl<<<(N_ + 63) / 64, 256, GEMM_SHM>>>(h_ptr, W_l + 128 * 128, instr + B_ * 64, batch,
                                               att_l + 128, att_r + 128, 1, bn_gamma, bn_beta);
    agg_kernel<<<1280, 256>>>(1, h_ptr, out, bias, 0, 1, bn_gamma, bn_beta);
}